// round 6
// baseline (speedup 1.0000x reference)
#include <cuda_runtime.h>
#include <math.h>

#define V_MAX   100000
#define E_MAX   1600000
#define IN_CH   128
#define HEADS   4
#define HC      64
#define NEG_SLOPE 0.2f
#define SCAN_BLK 256
#define XT_PAD  66              // xsT row stride (floats)

// ---------------- scratch (device globals; no allocation) ----------------
__device__ float g_z[(size_t)V_MAX * HC];     // projected features  [V,64]
__device__ float g_esrc[V_MAX * HEADS];       // per-node src logits [V,4]
__device__ float g_edst[V_MAX * HEADS];       // per-node dst logits [V,4]
__device__ int   g_deg[V_MAX];                // in-degree per node
__device__ int   g_excl[V_MAX];               // block-local exclusive scan
__device__ int   g_bsums[512];                // per-block sums
__device__ int   g_rowstart[V_MAX];           // CSR row offsets
__device__ int   g_cursor[V_MAX];             // scatter cursors
__device__ int   g_csr_src[E_MAX];            // src node per CSR slot

#define FMA_F32X2(d, a, b) \
    asm("fma.rn.f32x2 %0, %1, %2, %0;" : "+l"(d) : "l"(a), "l"(b))

// ---------------- CSR build ----------------
__global__ void zero_deg_kernel(int v) {
    int i = blockIdx.x * blockDim.x + threadIdx.x;
    if (i < v) g_deg[i] = 0;
}

__global__ void count_kernel(const int* __restrict__ ei, int ecnt) {
    int e = blockIdx.x * blockDim.x + threadIdx.x;
    if (e < ecnt) atomicAdd(&g_deg[ei[ecnt + e]], 1);
}

__global__ void scan1_kernel(int v) {
    __shared__ int sh[SCAN_BLK];
    int t = threadIdx.x;
    int i = blockIdx.x * SCAN_BLK + t;
    int val = (i < v) ? g_deg[i] : 0;
    sh[t] = val;
    __syncthreads();
#pragma unroll
    for (int off = 1; off < SCAN_BLK; off <<= 1) {
        int y = (t >= off) ? sh[t - off] : 0;
        __syncthreads();
        sh[t] += y;
        __syncthreads();
    }
    if (i < v) g_excl[i] = sh[t] - val;
    if (t == SCAN_BLK - 1) g_bsums[blockIdx.x] = sh[t];
}

// Fused block-offset + rowstart: each block reduces bsums[0..b-1] in smem.
__global__ void scan3_kernel(int v) {
    __shared__ int red[SCAN_BLK];
    const int b = blockIdx.x;
    const int t = threadIdx.x;
    int sum = 0;
    for (int i = t; i < b; i += SCAN_BLK) sum += g_bsums[i];
    red[t] = sum;
    __syncthreads();
#pragma unroll
    for (int off = SCAN_BLK / 2; off; off >>= 1) {
        if (t < off) red[t] += red[t + off];
        __syncthreads();
    }
    int prefix = red[0];
    int i = b * SCAN_BLK + t;
    if (i < v) {
        int r = g_excl[i] + prefix;
        g_rowstart[i] = r;
        g_cursor[i]   = r;
    }
}

__global__ void scatter_kernel(const int* __restrict__ ei, int ecnt) {
    int e = blockIdx.x * blockDim.x + threadIdx.x;
    if (e >= ecnt) return;
    int s = ei[e];
    int d = ei[ecnt + e];
    int pos = atomicAdd(&g_cursor[d], 1);
    g_csr_src[pos] = s;
}

// ---------------- fused GEMM + logits (packed f32x2 FMA) ----------------
// Tile 64 rows x 64 cols, K=128. blockDim (16,16), thread owns 4x4.
// smem: Ws2 = W splatted to {w,w} pairs, layout [k][j][tx] (conflict-free
// LDS.64); xsT = x tile transposed [k][row] so a row-pair is one LDS.64.
// Inner loop: 8 fma.rn.f32x2 per k (vs 16 FFMA) — bit-exact fp32.
__global__ void gemm_logits_kernel(const float* __restrict__ x,
                                   const float* __restrict__ W,
                                   const float* __restrict__ a_src,
                                   const float* __restrict__ a_dst,
                                   int v)
{
    extern __shared__ float sm[];
    float* Ws2 = sm;                          // 128 * 128 floats (64KB)
    float* xsT = Ws2 + IN_CH * HC * 2;        // 128 * XT_PAD floats
    float* as  = xsT + IN_CH * XT_PAD;        // 64
    float* ad  = as + 64;                     // 64

    const int tx = threadIdx.x, ty = threadIdx.y;
    const int tid = ty * 16 + tx;
    const int row0 = blockIdx.x * 64;

    // stage W splatted: channel c -> j = c&3, t = c>>2; pair at k*128+j*32+t*2
    for (int i = tid; i < IN_CH * HC; i += 256) {
        int k = i >> 6, c = i & 63;
        float w = W[i];
        int base = k * 128 + (c & 3) * 32 + (c >> 2) * 2;
        Ws2[base]     = w;
        Ws2[base + 1] = w;
    }
    if (tid < 64)       as[tid]      = a_src[tid];
    else if (tid < 128) ad[tid - 64] = a_dst[tid - 64];

    // stage x transposed: xsT[k][r] = x[row0+r][k]
    for (int i = tid; i < 64 * 32; i += 256) {
        int r = i >> 5, c4 = i & 31;
        float4 val = make_float4(0.f, 0.f, 0.f, 0.f);
        if (row0 + r < v)
            val = ((const float4*)x)[(size_t)(row0 + r) * 32 + c4];
        xsT[(c4 * 4 + 0) * XT_PAD + r] = val.x;
        xsT[(c4 * 4 + 1) * XT_PAD + r] = val.y;
        xsT[(c4 * 4 + 2) * XT_PAD + r] = val.z;
        xsT[(c4 * 4 + 3) * XT_PAD + r] = val.w;
    }
    __syncthreads();

    // packed accumulators: accP[p][j] = rows (ty*4+2p, ty*4+2p+1), channel tx*4+j
    unsigned long long accP[2][4];
#pragma unroll
    for (int p = 0; p < 2; ++p)
#pragma unroll
        for (int j = 0; j < 4; ++j) accP[p][j] = 0ULL;

#pragma unroll 4
    for (int k = 0; k < IN_CH; ++k) {
        unsigned long long x01 = *(const unsigned long long*)&xsT[k * XT_PAD + ty * 4];
        unsigned long long x23 = *(const unsigned long long*)&xsT[k * XT_PAD + ty * 4 + 2];
#pragma unroll
        for (int j = 0; j < 4; ++j) {
            unsigned long long wp =
                *(const unsigned long long*)&Ws2[k * 128 + j * 32 + tx * 2];
            FMA_F32X2(accP[0][j], x01, wp);
            FMA_F32X2(accP[1][j], x23, wp);
        }
    }

    // unpack
    float acc[4][4];
#pragma unroll
    for (int p = 0; p < 2; ++p)
#pragma unroll
        for (int j = 0; j < 4; ++j) {
            unsigned int lo, hi;
            asm("mov.b64 {%0,%1}, %2;" : "=r"(lo), "=r"(hi) : "l"(accP[p][j]));
            acc[p * 2 + 0][j] = __uint_as_float(lo);
            acc[p * 2 + 1][j] = __uint_as_float(hi);
        }

    const int h  = tx >> 2;
    const int c0 = (tx & 3) * 4;
#pragma unroll
    for (int i = 0; i < 4; ++i) {
        int row = row0 + ty * 4 + i;
        float ps = acc[i][0] * as[h * 16 + c0 + 0] + acc[i][1] * as[h * 16 + c0 + 1]
                 + acc[i][2] * as[h * 16 + c0 + 2] + acc[i][3] * as[h * 16 + c0 + 3];
        float pd = acc[i][0] * ad[h * 16 + c0 + 0] + acc[i][1] * ad[h * 16 + c0 + 1]
                 + acc[i][2] * ad[h * 16 + c0 + 2] + acc[i][3] * ad[h * 16 + c0 + 3];
        ps += __shfl_xor_sync(0xffffffffu, ps, 1);
        ps += __shfl_xor_sync(0xffffffffu, ps, 2);
        pd += __shfl_xor_sync(0xffffffffu, pd, 1);
        pd += __shfl_xor_sync(0xffffffffu, pd, 2);

        if (row < v) {
            *(float4*)&g_z[(size_t)row * HC + tx * 4] =
                make_float4(acc[i][0], acc[i][1], acc[i][2], acc[i][3]);
            if ((tx & 3) == 0) {
                g_esrc[row * HEADS + h] = ps;
                g_edst[row * HEADS + h] = pd;
            }
        }
    }
}

// ---------------- fused softmax + aggregation (CSR, smem-staged) ----------
__global__ void node_agg_kernel(float* __restrict__ out, int v) {
    __shared__ int   sh_s[8][32];
    __shared__ float sh_a[8][32][4];

    const int wid  = threadIdx.x >> 5;
    const int lane = threadIdx.x & 31;
    const int n = blockIdx.x * 8 + wid;
    if (n >= v) return;

    const int start = g_rowstart[n];
    const int degn  = g_deg[n];
    const float4 ed = *(const float4*)&g_edst[n * 4];
    const int head  = lane >> 3;

    float acc0 = 0.f, acc1 = 0.f;
    float d0 = 0.f, d1 = 0.f, d2 = 0.f, d3 = 0.f;

    for (int i0 = 0; i0 < degn; i0 += 32) {
        int idx = i0 + lane;
        int s = 0;
        float ex0 = 0.f, ex1 = 0.f, ex2 = 0.f, ex3 = 0.f;
        if (idx < degn) {
            s = __ldg(&g_csr_src[start + idx]);
            float4 es = *(const float4*)&g_esrc[s * 4];
            float w;
            w = es.x + ed.x; w = w > 0.f ? w : NEG_SLOPE * w; ex0 = __expf(w);
            w = es.y + ed.y; w = w > 0.f ? w : NEG_SLOPE * w; ex1 = __expf(w);
            w = es.z + ed.z; w = w > 0.f ? w : NEG_SLOPE * w; ex2 = __expf(w);
            w = es.w + ed.w; w = w > 0.f ? w : NEG_SLOPE * w; ex3 = __expf(w);
        }
        d0 += ex0; d1 += ex1; d2 += ex2; d3 += ex3;
        sh_s[wid][lane] = s;
        *(float4*)&sh_a[wid][lane][0] = make_float4(ex0, ex1, ex2, ex3);
        __syncwarp();

        int cnt = degn - i0; if (cnt > 32) cnt = 32;
        const float* zb = g_z + (size_t)lane * 2;
        int j = 0;
        for (; j + 4 <= cnt; j += 4) {
            int s0 = sh_s[wid][j + 0];
            int s1 = sh_s[wid][j + 1];
            int s2 = sh_s[wid][j + 2];
            int s3 = sh_s[wid][j + 3];
            float2 z0 = *(const float2*)(zb + (size_t)s0 * HC);
            float2 z1 = *(const float2*)(zb + (size_t)s1 * HC);
            float2 z2 = *(const float2*)(zb + (size_t)s2 * HC);
            float2 z3 = *(const float2*)(zb + (size_t)s3 * HC);
            float a0 = sh_a[wid][j + 0][head];
            float a1 = sh_a[wid][j + 1][head];
            float a2 = sh_a[wid][j + 2][head];
            float a3 = sh_a[wid][j + 3][head];
            acc0 += z0.x * a0; acc1 += z0.y * a0;
            acc0 += z1.x * a1; acc1 += z1.y * a1;
            acc0 += z2.x * a2; acc1 += z2.y * a2;
            acc0 += z3.x * a3; acc1 += z3.y * a3;
        }
        for (; j < cnt; ++j) {
            int sj = sh_s[wid][j];
            float a = sh_a[wid][j][head];
            float2 zv = *(const float2*)(zb + (size_t)sj * HC);
            acc0 += zv.x * a; acc1 += zv.y * a;
        }
        __syncwarp();
    }

#pragma unroll
    for (int o = 16; o; o >>= 1) {
        d0 += __shfl_xor_sync(0xffffffffu, d0, o);
        d1 += __shfl_xor_sync(0xffffffffu, d1, o);
        d2 += __shfl_xor_sync(0xffffffffu, d2, o);
        d3 += __shfl_xor_sync(0xffffffffu, d3, o);
    }
    float den = head == 0 ? d0 : head == 1 ? d1 : head == 2 ? d2 : d3;
    float r = __frcp_rn(den + 1e-9f);
    acc0 *= r; acc1 *= r;
    acc0 = acc0 > 0.f ? acc0 : expm1f(acc0);
    acc1 = acc1 > 0.f ? acc1 : expm1f(acc1);
    *(float2*)&out[(size_t)n * HC + lane * 2] = make_float2(acc0, acc1);
}

// ---------------- launch ----------------
extern "C" void kernel_launch(void* const* d_in, const int* in_sizes, int n_in,
                              void* d_out, int out_size) {
    const float* x     = (const float*)d_in[0];
    const int*   ei    = (const int*)d_in[1];
    const float* W     = (const float*)d_in[2];
    const float* a_src = (const float*)d_in[3];
    const float* a_dst = (const float*)d_in[4];
    float* out = (float*)d_out;

    int v    = in_sizes[0] / IN_CH;
    int ecnt = in_sizes[1] / 2;
    int nb   = (v + SCAN_BLK - 1) / SCAN_BLK;

    const int smem = (IN_CH * HC * 2 + IN_CH * XT_PAD + 128) * sizeof(float);
    cudaFuncSetAttribute(gemm_logits_kernel,
                         cudaFuncAttributeMaxDynamicSharedMemorySize, smem);

    zero_deg_kernel<<<(v + 255) / 256, 256>>>(v);
    count_kernel<<<(ecnt + 255) / 256, 256>>>(ei, ecnt);
    scan1_kernel<<<nb, SCAN_BLK>>>(v);
    scan3_kernel<<<nb, SCAN_BLK>>>(v);
    scatter_kernel<<<(ecnt + 255) / 256, 256>>>(ei, ecnt);
    gemm_logits_kernel<<<(v + 63) / 64, dim3(16, 16), smem>>>(x, W, a_src, a_dst, v);
    node_agg_kernel<<<(v + 7) / 8, 256>>>(out, v);
}

// round 7
// speedup vs baseline: 1.2831x; 1.2831x over previous
#include <cuda_runtime.h>
#include <math.h>

#define V_MAX   100000
#define E_MAX   1600000
#define IN_CH   128
#define HEADS   4
#define HC      64
#define NEG_SLOPE 0.2f
#define SCAN_BLK 256

// ---------------- scratch (device globals; no allocation) ----------------
__device__ float g_z[(size_t)V_MAX * HC];     // projected features  [V,64]
__device__ float g_esrc[V_MAX * HEADS];       // per-node src logits [V,4]
__device__ float g_edst[V_MAX * HEADS];       // per-node dst logits [V,4]
__device__ int   g_deg[V_MAX];                // in-degree per node
__device__ int   g_excl[V_MAX];               // block-local exclusive scan
__device__ int   g_bsums[512];                // per-block sums
__device__ int   g_rowstart[V_MAX];           // CSR row offsets
__device__ int   g_cursor[V_MAX];             // scatter cursors
__device__ int   g_csr_src[E_MAX];            // src node per CSR slot

// ---------------- CSR build ----------------
__global__ void zero_deg_kernel(int v) {
    int i = blockIdx.x * blockDim.x + threadIdx.x;
    if (i < v) g_deg[i] = 0;
}

__global__ void count_kernel(const int* __restrict__ ei, int ecnt) {
    int e = blockIdx.x * blockDim.x + threadIdx.x;
    if (e < ecnt) atomicAdd(&g_deg[ei[ecnt + e]], 1);
}

__global__ void scan1_kernel(int v) {
    __shared__ int sh[SCAN_BLK];
    int t = threadIdx.x;
    int i = blockIdx.x * SCAN_BLK + t;
    int val = (i < v) ? g_deg[i] : 0;
    sh[t] = val;
    __syncthreads();
#pragma unroll
    for (int off = 1; off < SCAN_BLK; off <<= 1) {
        int y = (t >= off) ? sh[t - off] : 0;
        __syncthreads();
        sh[t] += y;
        __syncthreads();
    }
    if (i < v) g_excl[i] = sh[t] - val;
    if (t == SCAN_BLK - 1) g_bsums[blockIdx.x] = sh[t];
}

// Fused block-offset + rowstart: each block reduces bsums[0..b-1] in smem.
__global__ void scan3_kernel(int v) {
    __shared__ int red[SCAN_BLK];
    const int b = blockIdx.x;
    const int t = threadIdx.x;
    int sum = 0;
    for (int i = t; i < b; i += SCAN_BLK) sum += g_bsums[i];
    red[t] = sum;
    __syncthreads();
#pragma unroll
    for (int off = SCAN_BLK / 2; off; off >>= 1) {
        if (t < off) red[t] += red[t + off];
        __syncthreads();
    }
    int prefix = red[0];
    int i = b * SCAN_BLK + t;
    if (i < v) {
        int r = g_excl[i] + prefix;
        g_rowstart[i] = r;
        g_cursor[i]   = r;
    }
}

__global__ void scatter_kernel(const int* __restrict__ ei, int ecnt) {
    int e = blockIdx.x * blockDim.x + threadIdx.x;
    if (e >= ecnt) return;
    int s = ei[e];
    int d = ei[ecnt + e];
    int pos = atomicAdd(&g_cursor[d], 1);
    g_csr_src[pos] = s;
}

// ---------------- fused GEMM + logits (R4-proven version) ----------------
__global__ void gemm_logits_kernel(const float* __restrict__ x,
                                   const float* __restrict__ W,
                                   const float* __restrict__ a_src,
                                   const float* __restrict__ a_dst,
                                   int v)
{
    extern __shared__ float sm[];
    float* Ws = sm;
    float* xs = Ws + IN_CH * HC;
    float* as = xs + 64 * 132;
    float* ad = as + 64;

    const int tx = threadIdx.x, ty = threadIdx.y;
    const int tid = ty * 16 + tx;
    const int row0 = blockIdx.x * 64;

    for (int i = tid; i < (IN_CH * HC) / 4; i += 256)
        ((float4*)Ws)[i] = ((const float4*)W)[i];
    if (tid < 64)       as[tid]      = a_src[tid];
    else if (tid < 128) ad[tid - 64] = a_dst[tid - 64];

    for (int i = tid; i < 64 * 32; i += 256) {
        int r = i >> 5, c4 = i & 31;
        float4 val = make_float4(0.f, 0.f, 0.f, 0.f);
        if (row0 + r < v)
            val = ((const float4*)x)[(size_t)(row0 + r) * 32 + c4];
        *(float4*)&xs[r * 132 + c4 * 4] = val;
    }
    __syncthreads();

    float acc[4][4];
#pragma unroll
    for (int i = 0; i < 4; ++i)
#pragma unroll
        for (int j = 0; j < 4; ++j) acc[i][j] = 0.f;

#pragma unroll 8
    for (int k = 0; k < IN_CH; ++k) {
        float4 wv = ((float4*)Ws)[k * 16 + tx];
#pragma unroll
        for (int i = 0; i < 4; ++i) {
            float xv = xs[(ty * 4 + i) * 132 + k];
            acc[i][0] += xv * wv.x;
            acc[i][1] += xv * wv.y;
            acc[i][2] += xv * wv.z;
            acc[i][3] += xv * wv.w;
        }
    }

    const int h  = tx >> 2;
    const int c0 = (tx & 3) * 4;
#pragma unroll
    for (int i = 0; i < 4; ++i) {
        int row = row0 + ty * 4 + i;
        float ps = acc[i][0] * as[h * 16 + c0 + 0] + acc[i][1] * as[h * 16 + c0 + 1]
                 + acc[i][2] * as[h * 16 + c0 + 2] + acc[i][3] * as[h * 16 + c0 + 3];
        float pd = acc[i][0] * ad[h * 16 + c0 + 0] + acc[i][1] * ad[h * 16 + c0 + 1]
                 + acc[i][2] * ad[h * 16 + c0 + 2] + acc[i][3] * ad[h * 16 + c0 + 3];
        ps += __shfl_xor_sync(0xffffffffu, ps, 1);
        ps += __shfl_xor_sync(0xffffffffu, ps, 2);
        pd += __shfl_xor_sync(0xffffffffu, pd, 1);
        pd += __shfl_xor_sync(0xffffffffu, pd, 2);

        if (row < v) {
            *(float4*)&g_z[(size_t)row * HC + tx * 4] =
                make_float4(acc[i][0], acc[i][1], acc[i][2], acc[i][3]);
            if ((tx & 3) == 0) {
                g_esrc[row * HEADS + h] = ps;
                g_edst[row * HEADS + h] = pd;
            }
        }
    }
}

// ---------------- fused softmax + aggregation (CSR, smem-staged) ----------
__global__ void node_agg_kernel(float* __restrict__ out, int v) {
    __shared__ int   sh_s[8][32];
    __shared__ float sh_a[8][32][4];

    const int wid  = threadIdx.x >> 5;
    const int lane = threadIdx.x & 31;
    const int n = blockIdx.x * 8 + wid;
    if (n >= v) return;

    const int start = g_rowstart[n];
    const int degn  = g_deg[n];
    const float4 ed = *(const float4*)&g_edst[n * 4];
    const int head  = lane >> 3;

    float acc0 = 0.f, acc1 = 0.f;
    float d0 = 0.f, d1 = 0.f, d2 = 0.f, d3 = 0.f;

    for (int i0 = 0; i0 < degn; i0 += 32) {
        int idx = i0 + lane;
        int s = 0;
        float ex0 = 0.f, ex1 = 0.f, ex2 = 0.f, ex3 = 0.f;
        if (idx < degn) {
            s = __ldg(&g_csr_src[start + idx]);
            float4 es = *(const float4*)&g_esrc[s * 4];
            float w;
            w = es.x + ed.x; w = w > 0.f ? w : NEG_SLOPE * w; ex0 = __expf(w);
            w = es.y + ed.y; w = w > 0.f ? w : NEG_SLOPE * w; ex1 = __expf(w);
            w = es.z + ed.z; w = w > 0.f ? w : NEG_SLOPE * w; ex2 = __expf(w);
            w = es.w + ed.w; w = w > 0.f ? w : NEG_SLOPE * w; ex3 = __expf(w);
        }
        d0 += ex0; d1 += ex1; d2 += ex2; d3 += ex3;
        sh_s[wid][lane] = s;
        *(float4*)&sh_a[wid][lane][0] = make_float4(ex0, ex1, ex2, ex3);
        __syncwarp();

        int cnt = degn - i0; if (cnt > 32) cnt = 32;
        const float* zb = g_z + (size_t)lane * 2;
        int j = 0;
        // 8-deep unroll: 8 independent LDG.64 gathers in flight per lane.
        for (; j + 8 <= cnt; j += 8) {
            int    sj[8];
            float2 zj[8];
            float  aj[8];
#pragma unroll
            for (int u = 0; u < 8; ++u) sj[u] = sh_s[wid][j + u];
#pragma unroll
            for (int u = 0; u < 8; ++u) zj[u] = *(const float2*)(zb + (size_t)sj[u] * HC);
#pragma unroll
            for (int u = 0; u < 8; ++u) aj[u] = sh_a[wid][j + u][head];
#pragma unroll
            for (int u = 0; u < 8; ++u) {
                acc0 += zj[u].x * aj[u];
                acc1 += zj[u].y * aj[u];
            }
        }
        for (; j < cnt; ++j) {
            int sj = sh_s[wid][j];
            float a = sh_a[wid][j][head];
            float2 zv = *(const float2*)(zb + (size_t)sj * HC);
            acc0 += zv.x * a; acc1 += zv.y * a;
        }
        __syncwarp();
    }

#pragma unroll
    for (int o = 16; o; o >>= 1) {
        d0 += __shfl_xor_sync(0xffffffffu, d0, o);
        d1 += __shfl_xor_sync(0xffffffffu, d1, o);
        d2 += __shfl_xor_sync(0xffffffffu, d2, o);
        d3 += __shfl_xor_sync(0xffffffffu, d3, o);
    }
    float den = head == 0 ? d0 : head == 1 ? d1 : head == 2 ? d2 : d3;
    float r = __frcp_rn(den + 1e-9f);
    acc0 *= r; acc1 *= r;
    acc0 = acc0 > 0.f ? acc0 : expm1f(acc0);
    acc1 = acc1 > 0.f ? acc1 : expm1f(acc1);
    *(float2*)&out[(size_t)n * HC + lane * 2] = make_float2(acc0, acc1);
}

// ---------------- launch ----------------
// NOTE: gemm is independent of the CSR build, so it is launched 4th — the
// profiler has consistently sampled launch #4, and we want GEMM evidence.
extern "C" void kernel_launch(void* const* d_in, const int* in_sizes, int n_in,
                              void* d_out, int out_size) {
    const float* x     = (const float*)d_in[0];
    const int*   ei    = (const int*)d_in[1];
    const float* W     = (const float*)d_in[2];
    const float* a_src = (const float*)d_in[3];
    const float* a_dst = (const float*)d_in[4];
    float* out = (float*)d_out;

    int v    = in_sizes[0] / IN_CH;
    int ecnt = in_sizes[1] / 2;
    int nb   = (v + SCAN_BLK - 1) / SCAN_BLK;

    const int smem = (IN_CH * HC + 64 * 132 + 128) * sizeof(float);
    cudaFuncSetAttribute(gemm_logits_kernel,
                         cudaFuncAttributeMaxDynamicSharedMemorySize, smem);

    zero_deg_kernel<<<(v + 255) / 256, 256>>>(v);
    count_kernel<<<(ecnt + 255) / 256, 256>>>(ei, ecnt);
    scan1_kernel<<<nb, SCAN_BLK>>>(v);
    gemm_logits_kernel<<<(v + 63) / 64, dim3(16, 16), smem>>>(x, W, a_src, a_dst, v);
    scan3_kernel<<<nb, SCAN_BLK>>>(v);
    scatter_kernel<<<(ecnt + 255) / 256, 256>>>(ei, ecnt);
    node_agg_kernel<<<(v + 7) / 8, 256>>>(out, v);
}